// round 1
// baseline (speedup 1.0000x reference)
#include <cuda_runtime.h>
#include <cuda_bf16.h>

#define BW 1280
#define BH 720
#define BB 32

__global__ __launch_bounds__(256) void warp_disp_kernel(
    const float* __restrict__ img,
    const float* __restrict__ disp,
    float* __restrict__ out)
{
    const int totalq = BB * BH * BW / 4;
    int tid = blockIdx.x * blockDim.x + threadIdx.x;   // one thread = 4 pixels
    if (tid >= totalq) return;

    int p    = tid * 4;
    int x    = p % BW;          // BW % 4 == 0 -> all 4 pixels share a row
    int rest = p / BW;
    int y    = rest % BH;
    int b    = rest / BH;

    // ---- vertical terms: depend only on y (disp shifts x only) ----
    float gy  = ((float)y - (BH - 1) * 0.5f) / (float)(BH - 1) * 2.0f;
    float iy  = ((gy + 1.0f) * (float)BH - 1.0f) * 0.5f;
    float y0f = floorf(iy);
    float wy1 = iy - y0f;
    float wy0 = 1.0f - wy1;
    int   y0  = (int)y0f;
    int   y1  = y0 + 1;
    bool  vy0 = (y0 >= 0) && (y0 < BH);
    bool  vy1 = (y1 >= 0) && (y1 < BH);

    const float* imgb = img + (size_t)b * (BH * BW);
    const float* row0 = imgb + (size_t)y0 * BW;
    const float* row1 = imgb + (size_t)y1 * BW;

    float4 d4 = *reinterpret_cast<const float4*>(disp + p);
    float dv[4] = {d4.x, d4.y, d4.z, d4.w};
    float res[4];

#pragma unroll
    for (int i = 0; i < 4; i++) {
        // ---- horizontal terms: exact reference arithmetic order ----
        float gx  = (float)(x + i) - dv[i];
        gx = (gx - (BW - 1) * 0.5f) / (float)(BW - 1) * 2.0f;
        float ix  = ((gx + 1.0f) * (float)BW - 1.0f) * 0.5f;
        float x0f = floorf(ix);
        float wx1 = ix - x0f;
        float wx0 = 1.0f - wx1;
        int   x0  = (int)x0f;
        int   x1  = x0 + 1;
        bool  vx0 = (x0 >= 0) && (x0 < BW);
        bool  vx1 = (x1 >= 0) && (x1 < BW);

        float v00 = (vy0 && vx0) ? __ldg(row0 + x0) : 0.0f;
        float v01 = (vy0 && vx1) ? __ldg(row0 + x1) : 0.0f;
        float v10 = (vy1 && vx0) ? __ldg(row1 + x0) : 0.0f;
        float v11 = (vy1 && vx1) ? __ldg(row1 + x1) : 0.0f;

        res[i] = v00 * (wy0 * wx0) + v01 * (wy0 * wx1)
               + v10 * (wy1 * wx0) + v11 * (wy1 * wx1);
    }

    *reinterpret_cast<float4*>(out + p) = make_float4(res[0], res[1], res[2], res[3]);
}

extern "C" void kernel_launch(void* const* d_in, const int* in_sizes, int n_in,
                              void* d_out, int out_size)
{
    const float* right_img = (const float*)d_in[0];
    const float* disp      = (const float*)d_in[1];
    float*       out       = (float*)d_out;

    const int totalq = BB * BH * BW / 4;      // 7,372,800 threads
    const int threads = 256;
    const int blocks  = (totalq + threads - 1) / threads;
    warp_disp_kernel<<<blocks, threads>>>(right_img, disp, out);
}

// round 2
// speedup vs baseline: 1.0563x; 1.0563x over previous
#include <cuda_runtime.h>
#include <cuda_bf16.h>

#define IW 1280
#define IH 720
#define IB 32

#define PADL 68                 // left zero pad (covers x0 >= -65), 16B aligned
#define PADR 4                  // right zero pad (covers x1 <= 1280)
#define ROWF (PADL + IW + PADR) // 1352 floats per smem row (16B-aligned stride)

__global__ __launch_bounds__(320) void warp_disp_smem(
    const float* __restrict__ img,
    const float* __restrict__ disp,
    float* __restrict__ out)
{
    __shared__ float sm[2 * ROWF];

    const int blk = blockIdx.x;     // = b*IH + y
    const int y   = blk % IH;
    const int b   = blk / IH;
    const int t   = threadIdx.x;    // 320 threads; thread t handles x = 4t..4t+3

    // ---- vertical terms (uniform per block): iy = y*H/(H-1) - 0.5 ----
    float iy  = fmaf((float)y, (float)IH / (float)(IH - 1), -0.5f);
    float y0f = floorf(iy);
    float wy1 = iy - y0f;
    float wy0 = 1.0f - wy1;
    int   y0  = (int)y0f;
    int   y1  = y0 + 1;
    bool  vy0 = (unsigned)y0 < (unsigned)IH;
    bool  vy1 = (unsigned)y1 < (unsigned)IH;
    int   yc0 = vy0 ? y0 : 0;
    int   yc1 = vy1 ? y1 : (IH - 1);

    const float* imgb = img + (size_t)b * (IH * IW);
    const float4* g0  = (const float4*)(imgb + yc0 * IW);
    const float4* g1  = (const float4*)(imgb + yc1 * IW);

    // prefetch disp early (overlaps staging latency)
    const int p = blk * IW + t * 4;
    float4 d4 = *reinterpret_cast<const float4*>(disp + p);

    // ---- stage two rows into smem (zeros if the row is out of range) ----
    float4 z4 = make_float4(0.f, 0.f, 0.f, 0.f);
    float4 r0v = vy0 ? g0[t] : z4;
    float4 r1v = vy1 ? g1[t] : z4;

    float4* s0q = (float4*)(sm);
    float4* s1q = (float4*)(sm + ROWF);
    s0q[PADL / 4 + t] = r0v;        // data region: float4 slots [17, 337)
    s1q[PADL / 4 + t] = r1v;
    if (t < 18) {                   // zero pads: slots 0..16 (left) and 337 (right)
        int zi = (t == 17) ? (ROWF / 4 - 1) : t;
        s0q[zi] = z4;
        s1q[zi] = z4;
    }
    __syncthreads();

    // ---- per-pixel: ix = u*W/(W-1) - 0.5, gather 4 taps from smem ----
    const float* s0 = sm + PADL;
    const float* s1 = sm + ROWF + PADL;
    const float Ax = (float)IW / (float)(IW - 1);

    float dv[4] = {d4.x, d4.y, d4.z, d4.w};
    float res[4];
    const int xbase = t * 4;

#pragma unroll
    for (int i = 0; i < 4; i++) {
        float u   = (float)(xbase + i) - dv[i];
        float ix  = fmaf(u, Ax, -0.5f);
        float x0f = floorf(ix);
        float wx1 = ix - x0f;
        float wx0 = 1.0f - wx1;
        int   x0  = (int)x0f;       // in [-65, 1279] given disp in [0,64)

        float v00 = s0[x0];
        float v01 = s0[x0 + 1];
        float v10 = s1[x0];
        float v11 = s1[x0 + 1];

        float h0 = fmaf(v01, wx1, v00 * wx0);
        float h1 = fmaf(v11, wx1, v10 * wx0);
        res[i]   = fmaf(h1, wy1, h0 * wy0);
    }

    *reinterpret_cast<float4*>(out + p) = make_float4(res[0], res[1], res[2], res[3]);
}

extern "C" void kernel_launch(void* const* d_in, const int* in_sizes, int n_in,
                              void* d_out, int out_size)
{
    const float* right_img = (const float*)d_in[0];
    const float* disp      = (const float*)d_in[1];
    float*       out       = (float*)d_out;

    const int blocks = IB * IH;     // 23040 CTAs, one per output row
    warp_disp_smem<<<blocks, 320>>>(right_img, disp, out);
}